// round 12
// baseline (speedup 1.0000x reference)
#include <cuda_runtime.h>
#include <cuda_bf16.h>

// Echo state network, fully fused into ONE kernel.
//   proj = x.reshape(7168,28) @ W_in^T ; h_{t+1} = tanh(proj_t + W_res h_t)
//   h_last[b] = h after step b*28+27 ; out = h_last @ W_out^T + b_out
//
// Scan trick (sm_103a): BAR.SYNC is deferred-blocking. Each thread's W_res row
// is ROTATED by 32*warp so the first 32 columns are its own warp's h values,
// fed by register shuffles (no smem) -> that FMA work executes inside the
// barrier-drain window; the remaining 96 columns come via LDS afterwards.

#define HIDDEN   128
#define T_STEPS  7168
#define SEQ      28
#define BATCH    256
#define NOUT     10
#define NBLK     112        // T_STEPS / 64

typedef unsigned long long ull;

// +2 zero pad rows -> unconditional prefetch in the scan
__device__ float g_proj[(T_STEPS + 2) * HIDDEN];
__device__ float g_hlast[BATCH * HIDDEN];
__device__ int   g_sync;

// -------- packed f32x2 helpers (sm_100+) --------
__device__ __forceinline__ ull pack2(float lo, float hi) {
    ull r;
    asm("mov.b64 %0, {%1, %2};" : "=l"(r) : "f"(lo), "f"(hi));
    return r;
}
__device__ __forceinline__ void unpack2(ull v, float& lo, float& hi) {
    asm("mov.b64 {%0, %1}, %2;" : "=f"(lo), "=f"(hi) : "l"(v));
}
__device__ __forceinline__ ull ffma2(ull a, ull b, ull c) {
    ull d;
    asm("fma.rn.f32x2 %0, %1, %2, %3;" : "=l"(d) : "l"(a), "l"(b), "l"(c));
    return d;
}
__device__ __forceinline__ ull fadd2(ull a, ull b) {
    ull d;
    asm("add.rn.f32x2 %0, %1, %2;" : "=l"(d) : "l"(a), "l"(b));
    return d;
}
__device__ __forceinline__ float ex2_approx(float x) {
    float y;
    asm("ex2.approx.f32 %0, %1;" : "=f"(y) : "f"(x));
    return y;
}
__device__ __forceinline__ float rcp_approx(float x) {
    float y;
    asm("rcp.approx.f32 %0, %1;" : "=f"(y) : "f"(x));
    return y;
}

// K2 = 2*log2(e). W_res and proj PRE-SCALED by K2 so the accumulated value is
// u' = K2*(p + W h); tanh = 1 - 2/(2^{u'}+1). |u'| bounded -> finite fp32.
#define K2SCALE 2.885390081777927f

__global__ __launch_bounds__(128, 1) void esn_fused_kernel(
    const float* __restrict__ x,     const float* __restrict__ W_in,
    const float* __restrict__ W_res, const float* __restrict__ W_out,
    const float* __restrict__ b_out, float* __restrict__ out)
{
    __shared__ float sx[64 * SEQ];                    // x tile (proj phase)
    // double-buffered, DUPLICATED h (rotation reads span [ROT, ROT+128))
    __shared__ __align__(16) float hbuf[2][256];

    const int i   = threadIdx.x;                      // hidden row (0..127)
    const int blk = blockIdx.x;
    const int ROT = i & 96;                           // 32 * warp_id

    // ================= Phase 1: proj slice (pre-scaled by K2) =================
    {
        const int t0 = blk * 64;
        float wi[SEQ];
        #pragma unroll
        for (int d = 0; d < SEQ; d++) wi[d] = __ldg(&W_in[i * SEQ + d]) * K2SCALE;

        for (int k = i; k < 64 * SEQ; k += 128) sx[k] = x[t0 * SEQ + k];
        __syncthreads();

        #pragma unroll 4
        for (int tl = 0; tl < 64; tl++) {
            const float* xr = &sx[tl * SEQ];          // broadcast
            float a = 0.f;
            #pragma unroll
            for (int d = 0; d < SEQ; d++) a = fmaf(xr[d], wi[d], a);
            g_proj[(t0 + tl) * HIDDEN + i] = a;       // coalesced
        }
    }

    __threadfence();
    __syncthreads();
    if (i == 0) atomicAdd(&g_sync, 1);
    if (blk != 0) return;

    // ==== Block 0: load W_res row ROTATED by ROT (overlaps the spin) ====
    // w[j] multiplies h[(ROT + 2j) & 127 .. +1]; own-warp block = w[0..15].
    ull w[64];
    {
        const float* wrow = W_res + i * HIDDEN;
        #pragma unroll
        for (int j = 0; j < 64; j++) {
            int col = (ROT + 2 * j) & 127;
            float2 v = *(const float2*)(wrow + col);
            w[j] = pack2(v.x * K2SCALE, v.y * K2SCALE);
        }
    }

    if (i == 0) {
        while (atomicAdd(&g_sync, 0) < NBLK) { }
        atomicExch(&g_sync, 0);                       // reset for next replay
    }
    __syncthreads();
    __threadfence();

    // ================= Phase 2: serial scan =================
    float hn = 0.f;                                   // my h value (lane-owned)
    float pc = __ldcg(&g_proj[i]);
    float pn = __ldcg(&g_proj[HIDDEN + i]);
    const float* pptr = &g_proj[2 * HIDDEN + i];
    int cnt = SEQ, batch = 0;

    for (int t = 0; t < T_STEPS; t++) {
        float* hb = hbuf[t & 1];
        hb[i] = hn;                                   // both copies (rotation wrap)
        hb[i + 128] = hn;
        float pf = __ldcg(pptr);                      // pad rows -> no guard
        pptr += HIDDEN;
        __syncthreads();                              // DEFER_BLOCKING

        // ---- own-warp block via shuffles (no smem: runs in bar-drain window)
        ull a0 = pack2(pc, 0.f), a1 = 0ull, a2 = 0ull, a3 = 0ull;
        #pragma unroll
        for (int p = 0; p < 16; p++) {
            float h0 = __shfl_sync(0xffffffffu, hn, 2 * p);
            float h1 = __shfl_sync(0xffffffffu, hn, 2 * p + 1);
            ull hv = pack2(h0, h1);
            switch (p & 3) {
                case 0: a0 = ffma2(w[p], hv, a0); break;
                case 1: a1 = ffma2(w[p], hv, a1); break;
                case 2: a2 = ffma2(w[p], hv, a2); break;
                default: a3 = ffma2(w[p], hv, a3); break;
            }
        }

        // ---- remaining 96 values via LDS (24 x LDS.128 + 48 x f32x2-FMA)
        const ulonglong2* h2 = ((const ulonglong2*)hb) + (ROT >> 2) + 8;
        #pragma unroll
        for (int j = 0; j < 6; j++) {
            ulonglong2 v0 = h2[4 * j + 0];
            ulonglong2 v1 = h2[4 * j + 1];
            ulonglong2 v2 = h2[4 * j + 2];
            ulonglong2 v3 = h2[4 * j + 3];
            a0 = ffma2(w[16 + 8 * j + 0], v0.x, a0);
            a1 = ffma2(w[16 + 8 * j + 1], v0.y, a1);
            a2 = ffma2(w[16 + 8 * j + 2], v1.x, a2);
            a3 = ffma2(w[16 + 8 * j + 3], v1.y, a3);
            a0 = ffma2(w[16 + 8 * j + 4], v2.x, a0);
            a1 = ffma2(w[16 + 8 * j + 5], v2.y, a1);
            a2 = ffma2(w[16 + 8 * j + 6], v3.x, a2);
            a3 = ffma2(w[16 + 8 * j + 7], v3.y, a3);
        }

        // ---- reduce + tanh: tanh = 1 - 2/(e^{2u}+1)
        ull s01 = fadd2(a0, a1);
        ull s23 = fadd2(a2, a3);
        ull st  = fadd2(s01, s23);
        float lo, hi;
        unpack2(st, lo, hi);
        float e = ex2_approx(lo + hi);
        hn = fmaf(-2.0f, rcp_approx(e + 1.0f), 1.0f);

        if (--cnt == 0) {                             // end of batch: record state
            g_hlast[batch * HIDDEN + i] = hn;
            batch++;
            cnt = SEQ;
        }
        pc = pn;
        pn = pf;
    }

    // ================= Phase 3: output head =================
    __syncthreads();
    for (int e = i; e < BATCH * NOUT; e += 128) {
        int b = e / NOUT;
        int o = e - b * NOUT;
        const float* hr = g_hlast + b * HIDDEN;
        const float* wr = W_out + o * HIDDEN;
        float a = __ldg(&b_out[o]);
        #pragma unroll 8
        for (int h = 0; h < HIDDEN; h++)
            a = fmaf(hr[h], __ldg(&wr[h]), a);
        out[e] = a;
    }
}

extern "C" void kernel_launch(void* const* d_in, const int* in_sizes, int n_in,
                              void* d_out, int out_size)
{
    const float* x     = (const float*)d_in[0];
    const float* W_in  = (const float*)d_in[1];
    const float* W_res = (const float*)d_in[2];
    const float* W_out = (const float*)d_in[3];
    const float* b_out = (const float*)d_in[4];
    float* out = (float*)d_out;

    esn_fused_kernel<<<NBLK, 128>>>(x, W_in, W_res, W_out, b_out, out);
}

// round 15
// speedup vs baseline: 1.2066x; 1.2066x over previous
#include <cuda_runtime.h>
#include <cuda_bf16.h>

// Echo state network, fully fused into ONE kernel.
//   x (256,28,28) f32, W_in (128,28), W_res (128,128), W_out (10,128), b_out (10)
//   proj = x.reshape(7168,28) @ W_in^T                      (7168,128)
//   h_{t+1} = tanh(proj_t + W_res @ h_t)  t = 0..7167  (single serial state)
//   h_last[b] = h after step b*28+27 ; out = h_last @ W_out^T + b_out (256,10)
//
// Phase 1: all 112 blocks compute proj slices (64 timesteps each).
// Grid-sync via atomic counter; block 0 runs the serial scan
// (128 threads, W_res row per thread in registers) and the output head.
// Tail uses the native MUFU tanh.approx.f32 (sm_75+): 1 MUFU instead of the
// ex2/rcp chain -> ~24 cycles off the per-step serial critical path.

#define HIDDEN   128
#define T_STEPS  7168
#define SEQ      28
#define BATCH    256
#define NOUT     10
#define NBLK     112        // T_STEPS / 64

typedef unsigned long long ull;

// +2 zero pad rows (never written) -> unconditional prefetch in the scan
__device__ float g_proj[(T_STEPS + 2) * HIDDEN];
__device__ float g_hlast[BATCH * HIDDEN];
__device__ int   g_sync;

// -------- packed f32x2 helpers (sm_100+) --------
__device__ __forceinline__ ull pack2(float lo, float hi) {
    ull r;
    asm("mov.b64 %0, {%1, %2};" : "=l"(r) : "f"(lo), "f"(hi));
    return r;
}
__device__ __forceinline__ void unpack2(ull v, float& lo, float& hi) {
    asm("mov.b64 {%0, %1}, %2;" : "=f"(lo), "=f"(hi) : "l"(v));
}
__device__ __forceinline__ ull ffma2(ull a, ull b, ull c) {
    ull d;
    asm("fma.rn.f32x2 %0, %1, %2, %3;" : "=l"(d) : "l"(a), "l"(b), "l"(c));
    return d;
}
__device__ __forceinline__ ull fadd2(ull a, ull b) {
    ull d;
    asm("add.rn.f32x2 %0, %1, %2;" : "=l"(d) : "l"(a), "l"(b));
    return d;
}
__device__ __forceinline__ float tanh_mufu(float x) {
    float y;
    asm("tanh.approx.f32 %0, %1;" : "=f"(y) : "f"(x));
    return y;
}

__global__ __launch_bounds__(128, 1) void esn_fused_kernel(
    const float* __restrict__ x,     const float* __restrict__ W_in,
    const float* __restrict__ W_res, const float* __restrict__ W_out,
    const float* __restrict__ b_out, float* __restrict__ out)
{
    __shared__ float sx[64 * SEQ];                 // 7 KB x tile (proj phase)
    __shared__ __align__(16) float hbuf[2][HIDDEN];

    const int i   = threadIdx.x;
    const int blk = blockIdx.x;

    // ================= Phase 1: proj slice =================
    {
        const int t0 = blk * 64;
        float wi[SEQ];
        #pragma unroll
        for (int d = 0; d < SEQ; d++) wi[d] = __ldg(&W_in[i * SEQ + d]);

        for (int k = i; k < 64 * SEQ; k += 128) sx[k] = x[t0 * SEQ + k];
        __syncthreads();

        #pragma unroll 4
        for (int tl = 0; tl < 64; tl++) {
            const float* xr = &sx[tl * SEQ];       // broadcast
            float a = 0.f;
            #pragma unroll
            for (int d = 0; d < SEQ; d++) a = fmaf(xr[d], wi[d], a);
            g_proj[(t0 + tl) * HIDDEN + i] = a;    // coalesced
        }
    }

    // release: make proj stores visible, then signal
    __threadfence();
    __syncthreads();
    if (i == 0) atomicAdd(&g_sync, 1);
    if (blk != 0) return;

    // ============ Block 0: load W_res row (overlaps with the spin) ============
    ull w[64];
    {
        const float2* wrow = (const float2*)(W_res + i * HIDDEN);
        #pragma unroll
        for (int j = 0; j < 64; j++) {
            float2 v = wrow[j];
            w[j] = pack2(v.x, v.y);
        }
    }

    // acquire: wait for all 112 blocks, then reset counter for next replay
    if (i == 0) {
        while (atomicAdd(&g_sync, 0) < NBLK) { }
        atomicExch(&g_sync, 0);
    }
    __syncthreads();
    __threadfence();

    // ================= Phase 2: serial scan =================
    hbuf[0][i] = 0.f;
    __syncthreads();

    float pc = __ldcg(&g_proj[i]);
    float pn = __ldcg(&g_proj[HIDDEN + i]);
    const float* pptr = &g_proj[2 * HIDDEN + i];
    int cnt = 0, batch = 0;

    for (int t = 0; t < T_STEPS; t++) {
        float pf = __ldcg(pptr);                   // pad rows -> no guard
        pptr += HIDDEN;

        const ulonglong2* h2 = (const ulonglong2*)hbuf[t & 1];

        // 32 x LDS.128 + 64 x f32x2-FMA, 4 accumulators
        ull a0 = pack2(pc, 0.f), a1 = 0ull, a2 = 0ull, a3 = 0ull;
        #pragma unroll
        for (int j = 0; j < 8; j++) {
            ulonglong2 v0 = h2[4 * j + 0];
            ulonglong2 v1 = h2[4 * j + 1];
            ulonglong2 v2 = h2[4 * j + 2];
            ulonglong2 v3 = h2[4 * j + 3];
            a0 = ffma2(w[8 * j + 0], v0.x, a0);
            a1 = ffma2(w[8 * j + 1], v0.y, a1);
            a2 = ffma2(w[8 * j + 2], v1.x, a2);
            a3 = ffma2(w[8 * j + 3], v1.y, a3);
            a0 = ffma2(w[8 * j + 4], v2.x, a0);
            a1 = ffma2(w[8 * j + 5], v2.y, a1);
            a2 = ffma2(w[8 * j + 6], v3.x, a2);
            a3 = ffma2(w[8 * j + 7], v3.y, a3);
        }

        // reduce + native MUFU tanh
        ull s01 = fadd2(a0, a1);
        ull s23 = fadd2(a2, a3);
        ull st  = fadd2(s01, s23);
        float lo, hi;
        unpack2(st, lo, hi);
        float hn = tanh_mufu(lo + hi);

        hbuf[(t + 1) & 1][i] = hn;

        if (++cnt == SEQ) {                        // end of batch: record state
            cnt = 0;
            g_hlast[batch * HIDDEN + i] = hn;
            batch++;
        }

        pc = pn;
        pn = pf;
        __syncthreads();
    }

    // ================= Phase 3: output head =================
    __syncthreads();
    for (int e = i; e < BATCH * NOUT; e += 128) {
        int b = e / NOUT;
        int o = e - b * NOUT;
        const float* hr = g_hlast + b * HIDDEN;
        const float* wr = W_out + o * HIDDEN;
        float a = __ldg(&b_out[o]);
        #pragma unroll 8
        for (int h = 0; h < HIDDEN; h++)
            a = fmaf(hr[h], __ldg(&wr[h]), a);
        out[e] = a;
    }
}

extern "C" void kernel_launch(void* const* d_in, const int* in_sizes, int n_in,
                              void* d_out, int out_size)
{
    const float* x     = (const float*)d_in[0];
    const float* W_in  = (const float*)d_in[1];
    const float* W_res = (const float*)d_in[2];
    const float* W_out = (const float*)d_in[3];
    const float* b_out = (const float*)d_in[4];
    float* out = (float*)d_out;

    esn_fused_kernel<<<NBLK, 128>>>(x, W_in, W_res, W_out, b_out, out);
}